// round 1
// baseline (speedup 1.0000x reference)
#include <cuda_runtime.h>
#include <cuda_bf16.h>
#include <math.h>

// ---------------- problem constants ----------------
constexpr int kV   = 50280;
constexpr int kD   = 768;
constexpr int kNL  = 8;
constexpr int kDI  = 1536;
constexpr int kDS  = 16;
constexpr int kDC  = 4;
constexpr int kDTR = 48;
constexpr int kNC  = 4;
constexpr int kB   = 2;
constexpr int kL   = 1024;
constexpr int kDBC = kDTR + 2 * kDS;  // 80
constexpr float kEPS = 1e-5f;

constexpr int kRows = kB * kL;        // 2048 token rows

// ---------------- device scratch (no allocations allowed) ----------------
__device__ float g_x  [kRows * kD];        // residual stream
__device__ float g_xn [kRows * kD];        // rmsnorm output
__device__ float g_xz [kRows * 2 * kDI];   // in_proj output
__device__ float g_xc [kRows * kDI];       // conv+silu output
__device__ float g_dbc[kRows * kDBC];      // x_proj output
__device__ float g_dt [kRows * kDI];       // softplus(dt)
__device__ float g_y  [kRows * kDI];       // scan output (post-gate)

// ---------------- helpers ----------------
__device__ __forceinline__ float warp_sum(float v) {
#pragma unroll
    for (int o = 16; o > 0; o >>= 1) v += __shfl_xor_sync(0xffffffffu, v, o);
    return v;
}

// ---------------- embed gather ----------------
__global__ void embed_kernel(const int* __restrict__ ids,
                             const float* __restrict__ embed,
                             float* __restrict__ x) {
    int idx = blockIdx.x * blockDim.x + threadIdx.x;
    if (idx >= kRows * kD) return;
    int row = idx / kD;
    int d = idx - row * kD;
    x[idx] = embed[(size_t)ids[row] * kD + d];
}

// ---------------- rmsnorm: one block per row ----------------
__global__ void rmsnorm_kernel(const float* __restrict__ x,
                               const float* __restrict__ w,
                               float* __restrict__ out) {
    int row = blockIdx.x;
    const float* xr = x + (size_t)row * kD;
    float s = 0.f;
    for (int d = threadIdx.x; d < kD; d += blockDim.x) {
        float v = xr[d];
        s = fmaf(v, v, s);
    }
    s = warp_sum(s);
    __shared__ float sh[8];
    __shared__ float inv_s;
    int wid = threadIdx.x >> 5, lane = threadIdx.x & 31;
    if (lane == 0) sh[wid] = s;
    __syncthreads();
    if (wid == 0) {
        float t = (lane < (blockDim.x >> 5)) ? sh[lane] : 0.f;
        t = warp_sum(t);
        if (lane == 0) inv_s = rsqrtf(t / (float)kD + kEPS);
    }
    __syncthreads();
    float inv = inv_s;
    for (int d = threadIdx.x; d < kD; d += blockDim.x)
        out[(size_t)row * kD + d] = xr[d] * inv * w[d];
}

// ---------------- generic fp32 GEMM:  C[M,N] = A[M,K(lda)] @ Bw[N,K]^T ----------------
// EPI 0: store   EPI 1: C += result (residual accumulate)   EPI 2: softplus(result + bias[n])
template <int EPI>
__global__ void gemm_tn_kernel(const float* __restrict__ A, int lda,
                               const float* __restrict__ Bw,
                               float* __restrict__ C, int ldc,
                               const float* __restrict__ bias,
                               int M, int N, int K) {
    constexpr int BM = 64, BN = 64, BK = 16;
    __shared__ float As[BK][BM + 4];
    __shared__ float Bs[BK][BN + 4];
    const int tid = threadIdx.x;
    const int bm0 = blockIdx.y * BM;
    const int bn0 = blockIdx.x * BN;
    const int tx = tid & 15;        // n direction
    const int ty = tid >> 4;        // m direction
    float acc[4][4] = {};

    for (int k0 = 0; k0 < K; k0 += BK) {
#pragma unroll
        for (int t = tid; t < BM * BK; t += 256) {
            int m = t >> 4, k = t & 15;
            int gm = bm0 + m, gk = k0 + k;
            As[k][m] = (gm < M && gk < K) ? A[(size_t)gm * lda + gk] : 0.f;
        }
#pragma unroll
        for (int t = tid; t < BN * BK; t += 256) {
            int n = t >> 4, k = t & 15;
            int gn = bn0 + n, gk = k0 + k;
            Bs[k][n] = (gn < N && gk < K) ? Bw[(size_t)gn * K + gk] : 0.f;
        }
        __syncthreads();
#pragma unroll
        for (int k = 0; k < BK; k++) {
            float a[4], b[4];
#pragma unroll
            for (int i = 0; i < 4; i++) a[i] = As[k][ty * 4 + i];
#pragma unroll
            for (int j = 0; j < 4; j++) b[j] = Bs[k][tx * 4 + j];
#pragma unroll
            for (int i = 0; i < 4; i++)
#pragma unroll
                for (int j = 0; j < 4; j++)
                    acc[i][j] = fmaf(a[i], b[j], acc[i][j]);
        }
        __syncthreads();
    }

#pragma unroll
    for (int i = 0; i < 4; i++) {
        int gm = bm0 + ty * 4 + i;
        if (gm >= M) continue;
#pragma unroll
        for (int j = 0; j < 4; j++) {
            int gn = bn0 + tx * 4 + j;
            if (gn >= N) continue;
            float v = acc[i][j];
            if (EPI == 1) v += C[(size_t)gm * ldc + gn];
            if (EPI == 2) {
                v += bias[gn];
                v = fmaxf(v, 0.f) + log1pf(expf(-fabsf(v)));  // stable softplus
            }
            C[(size_t)gm * ldc + gn] = v;
        }
    }
}

// ---------------- causal depthwise conv (DC=4) + SiLU ----------------
__global__ void conv_silu_kernel(const float* __restrict__ xz,
                                 const float* __restrict__ cw,
                                 const float* __restrict__ cb,
                                 float* __restrict__ xc) {
    int idx = blockIdx.x * blockDim.x + threadIdx.x;
    if (idx >= kRows * kDI) return;
    int i = idx % kDI;
    int r = idx / kDI;          // b*L + l
    int l = r % kL;
    int b = r / kL;
    float acc = cb[i];
#pragma unroll
    for (int k = 0; k < kDC; k++) {
        int ls = l + k - (kDC - 1);
        if (ls >= 0)
            acc = fmaf(xz[((size_t)(b * kL + ls)) * (2 * kDI) + i], cw[i * kDC + k], acc);
    }
    // silu
    xc[idx] = acc / (1.f + __expf(-acc));
}

// ---------------- selective scan ----------------
// one thread per (batch, channel, state); 16 lanes reduce via shfl; depth-4 operand prefetch
__global__ void scan_kernel(const float* __restrict__ dt,
                            const float* __restrict__ xc,
                            const float* __restrict__ dbc,
                            const float* __restrict__ xz,
                            const float* __restrict__ A_log,
                            const float* __restrict__ D_skip,
                            float* __restrict__ y) {
    const int tid = threadIdx.x;
    const int s = tid & (kDS - 1);
    const int cglob = blockIdx.x * (blockDim.x / kDS) + (tid >> 4);
    const int b = cglob / kDI;
    const int i = cglob - b * kDI;

    const float a   = -__expf(A_log[i * kDS + s]);
    const float dsk = D_skip[i];

    constexpr int PF = 4;
    float fdt[PF], fx[PF], fB[PF], fC[PF];

    const size_t base_row = (size_t)b * kL;
#pragma unroll
    for (int j = 0; j < PF; j++) {
        size_t r = base_row + j;
        fdt[j] = dt [r * kDI + i];
        fx [j] = xc [r * kDI + i];
        fB [j] = dbc[r * kDBC + kDTR + s];
        fC [j] = dbc[r * kDBC + kDTR + kDS + s];
    }

    float h = 0.f;
#pragma unroll 4
    for (int l = 0; l < kL; l++) {
        const int slot = l & (PF - 1);
        float dt_t = fdt[slot];
        float x_t  = fx[slot];
        float Bt   = fB[slot];
        float Ct   = fC[slot];

        int ln = l + PF;
        if (ln < kL) {
            size_t r = base_row + ln;
            fdt[slot] = dt [r * kDI + i];
            fx [slot] = xc [r * kDI + i];
            fB [slot] = dbc[r * kDBC + kDTR + s];
            fC [slot] = dbc[r * kDBC + kDTR + kDS + s];
        }

        h = fmaf(h, __expf(dt_t * a), dt_t * x_t * Bt);
        float p = h * Ct;
        p += __shfl_xor_sync(0xffffffffu, p, 8);
        p += __shfl_xor_sync(0xffffffffu, p, 4);
        p += __shfl_xor_sync(0xffffffffu, p, 2);
        p += __shfl_xor_sync(0xffffffffu, p, 1);
        if (s == 0) {
            size_t r = base_row + l;
            float z = xz[r * (2 * kDI) + kDI + i];
            float yy = fmaf(x_t, dsk, p);
            yy *= z / (1.f + __expf(-z));
            y[r * kDI + i] = yy;
        }
    }
}

// ---------------- final head: mean over L + linear classifier ----------------
__global__ void head_kernel(const float* __restrict__ xn,
                            const float* __restrict__ cls_w,
                            const float* __restrict__ cls_b,
                            float* __restrict__ out) {
    int b = blockIdx.x;
    __shared__ float mean[kD];
    for (int d = threadIdx.x; d < kD; d += blockDim.x) {
        float s = 0.f;
        const float* p = xn + ((size_t)b * kL) * kD + d;
        for (int l = 0; l < kL; l++) s += p[(size_t)l * kD];
        mean[d] = s / (float)kL;
    }
    __syncthreads();
    if (threadIdx.x < kNC) {
        int c = threadIdx.x;
        float s = cls_b[c];
        for (int d = 0; d < kD; d++) s = fmaf(mean[d], cls_w[c * kD + d], s);
        out[b * kNC + c] = s;
    }
}

// ---------------- launch ----------------
extern "C" void kernel_launch(void* const* d_in, const int* in_sizes, int n_in,
                              void* d_out, int out_size) {
    const int*   input_ids = (const int*)  d_in[0];
    const float* embed     = (const float*)d_in[1];
    const float* norm_w    = (const float*)d_in[2];
    const float* in_proj_w = (const float*)d_in[3];
    const float* conv_w    = (const float*)d_in[4];
    const float* conv_b    = (const float*)d_in[5];
    const float* x_proj_w  = (const float*)d_in[6];
    const float* dt_proj_w = (const float*)d_in[7];
    const float* dt_proj_b = (const float*)d_in[8];
    const float* A_log     = (const float*)d_in[9];
    const float* D_skip    = (const float*)d_in[10];
    const float* out_proj_w= (const float*)d_in[11];
    const float* norm_f_w  = (const float*)d_in[12];
    const float* cls_w     = (const float*)d_in[13];
    const float* cls_b     = (const float*)d_in[14];
    float* out = (float*)d_out;

    float *px, *pxn, *pxz, *pxc, *pdbc, *pdt, *py;
    cudaGetSymbolAddress((void**)&px,   g_x);
    cudaGetSymbolAddress((void**)&pxn,  g_xn);
    cudaGetSymbolAddress((void**)&pxz,  g_xz);
    cudaGetSymbolAddress((void**)&pxc,  g_xc);
    cudaGetSymbolAddress((void**)&pdbc, g_dbc);
    cudaGetSymbolAddress((void**)&pdt,  g_dt);
    cudaGetSymbolAddress((void**)&py,   g_y);

    // embedding
    {
        int total = kRows * kD;
        embed_kernel<<<(total + 255) / 256, 256>>>(input_ids, embed, px);
    }

    for (int l = 0; l < kNL; l++) {
        const float* w_norm = norm_w    + (size_t)l * kD;
        const float* w_in   = in_proj_w + (size_t)l * 2 * kDI * kD;
        const float* w_cw   = conv_w    + (size_t)l * kDI * kDC;
        const float* w_cb   = conv_b    + (size_t)l * kDI;
        const float* w_xp   = x_proj_w  + (size_t)l * kDBC * kDI;
        const float* w_dtw  = dt_proj_w + (size_t)l * kDI * kDTR;
        const float* w_dtb  = dt_proj_b + (size_t)l * kDI;
        const float* w_Al   = A_log     + (size_t)l * kDI * kDS;
        const float* w_Dsk  = D_skip    + (size_t)l * kDI;
        const float* w_out  = out_proj_w+ (size_t)l * kD * kDI;

        // 1) rmsnorm
        rmsnorm_kernel<<<kRows, 256>>>(px, w_norm, pxn);

        // 2) in_proj: xz[2048,3072] = xn[2048,768] @ W^T
        {
            dim3 grid((2 * kDI + 63) / 64, (kRows + 63) / 64);
            gemm_tn_kernel<0><<<grid, 256>>>(pxn, kD, w_in, pxz, 2 * kDI, nullptr,
                                             kRows, 2 * kDI, kD);
        }

        // 3) conv + silu
        {
            int total = kRows * kDI;
            conv_silu_kernel<<<(total + 255) / 256, 256>>>(pxz, w_cw, w_cb, pxc);
        }

        // 4) x_proj: dbc[2048,80] = xc @ W^T
        {
            dim3 grid((kDBC + 63) / 64, (kRows + 63) / 64);
            gemm_tn_kernel<0><<<grid, 256>>>(pxc, kDI, w_xp, pdbc, kDBC, nullptr,
                                             kRows, kDBC, kDI);
        }

        // 5) dt: dt[2048,1536] = softplus(dbc[:, :48] @ dtw^T + dtb)
        {
            dim3 grid((kDI + 63) / 64, (kRows + 63) / 64);
            gemm_tn_kernel<2><<<grid, 256>>>(pdbc, kDBC, w_dtw, pdt, kDI, w_dtb,
                                             kRows, kDI, kDTR);
        }

        // 6) selective scan + D skip + SiLU gate
        {
            int blocks = (kB * kDI * kDS) / 256;   // 192
            scan_kernel<<<blocks, 256>>>(pdt, pxc, pdbc, pxz, w_Al, w_Dsk, py);
        }

        // 7) out_proj + residual: x[2048,768] += y @ W^T
        {
            dim3 grid((kD + 63) / 64, (kRows + 63) / 64);
            gemm_tn_kernel<1><<<grid, 256>>>(py, kDI, w_out, px, kD, nullptr,
                                             kRows, kD, kDI);
        }
    }

    // final norm + mean pool + classifier
    rmsnorm_kernel<<<kRows, 256>>>(px, norm_f_w, pxn);
    head_kernel<<<kB, 256>>>(pxn, cls_w, cls_b, out);
}

// round 2
// speedup vs baseline: 1.3292x; 1.3292x over previous
#include <cuda_runtime.h>
#include <cuda_bf16.h>
#include <math.h>

// ---------------- problem constants ----------------
constexpr int kV   = 50280;
constexpr int kD   = 768;
constexpr int kNL  = 8;
constexpr int kDI  = 1536;
constexpr int kDS  = 16;
constexpr int kDC  = 4;
constexpr int kDTR = 48;
constexpr int kNC  = 4;
constexpr int kB   = 2;
constexpr int kL   = 1024;
constexpr int kDBC = kDTR + 2 * kDS;  // 80
constexpr float kEPS = 1e-5f;

constexpr int kRows = kB * kL;        // 2048 token rows
constexpr int kXPChunks = 8;          // split-K chunks for x_proj
constexpr int kXPKC = kDI / kXPChunks; // 192

// ---------------- device scratch (no allocations allowed) ----------------
__device__ float g_x  [kRows * kD];        // residual stream
__device__ float g_xn [kRows * kD];        // rmsnorm output
__device__ float g_xz [kRows * 2 * kDI];   // in_proj output
__device__ float g_xc [kRows * kDI];       // conv+silu output
__device__ float g_dbc[kRows * kDBC];      // x_proj output
__device__ float g_dbp[kXPChunks * kRows * kDBC]; // x_proj split-K partials
__device__ float g_dt [kRows * kDI];       // softplus(dt)
__device__ float g_y  [kRows * kDI];       // scan output (post-gate)

// ---------------- helpers ----------------
__device__ __forceinline__ float warp_sum(float v) {
#pragma unroll
    for (int o = 16; o > 0; o >>= 1) v += __shfl_xor_sync(0xffffffffu, v, o);
    return v;
}

// ---------------- embed gather ----------------
__global__ void embed_kernel(const int* __restrict__ ids,
                             const float* __restrict__ embed,
                             float* __restrict__ x) {
    int idx = blockIdx.x * blockDim.x + threadIdx.x;   // float4 index
    int total = kRows * kD / 4;
    if (idx >= total) return;
    int row = idx / (kD / 4);
    int d4 = idx - row * (kD / 4);
    const float4* src = (const float4*)(embed + (size_t)ids[row] * kD);
    ((float4*)x)[idx] = src[d4];
}

// ---------------- rmsnorm: one block per row ----------------
__global__ void rmsnorm_kernel(const float* __restrict__ x,
                               const float* __restrict__ w,
                               float* __restrict__ out) {
    int row = blockIdx.x;
    const float* xr = x + (size_t)row * kD;
    float s = 0.f;
    for (int d = threadIdx.x; d < kD; d += blockDim.x) {
        float v = xr[d];
        s = fmaf(v, v, s);
    }
    s = warp_sum(s);
    __shared__ float sh[8];
    __shared__ float inv_s;
    int wid = threadIdx.x >> 5, lane = threadIdx.x & 31;
    if (lane == 0) sh[wid] = s;
    __syncthreads();
    if (wid == 0) {
        float t = (lane < (blockDim.x >> 5)) ? sh[lane] : 0.f;
        t = warp_sum(t);
        if (lane == 0) inv_s = rsqrtf(t / (float)kD + kEPS);
    }
    __syncthreads();
    float inv = inv_s;
    for (int d = threadIdx.x; d < kD; d += blockDim.x)
        out[(size_t)row * kD + d] = xr[d] * inv * w[d];
}

// =====================================================================
// High-throughput fp32 GEMM: C[M,N] = A[M,K(lda)] @ Bw[N,K]^T
//   BMt in {64,128}, BN=128, BK=8, 256 threads, thread tile (BMt/16)x8
//   double-buffered smem, float4 smem reads -> FFMA-bound
// EPI 0: store   EPI 1: C += result   EPI 2: softplus(result + bias[n])
// Requires: M % BMt == 0, K % 8 == 0, Bw rows 16B-aligned (K%4==0),
//           C rows 16B-aligned (ldc%4==0), N guard handled.
// =====================================================================
template <int EPI, int BMt>
__global__ __launch_bounds__(256)
void sgemm_tn_kernel(const float* __restrict__ A, int lda,
                     const float* __restrict__ Bw,
                     float* __restrict__ C, int ldc,
                     const float* __restrict__ bias,
                     int M, int N, int K) {
    constexpr int BN = 128, BK = 8;
    constexpr int MR = BMt / 16;              // 8 or 4 rows per thread
    constexpr int AE = BMt * BK / 256;        // A elems per thread (4 or 2)
    __shared__ float As[2][BK][BMt + 4];
    __shared__ float Bs[2][BK][BN + 4];

    const int tid = threadIdx.x;
    const int bm0 = blockIdx.y * BMt;
    const int bn0 = blockIdx.x * BN;
    const int tx = tid & 15;       // n
    const int ty = tid >> 4;       // m

    // B loader: one float4 per thread along K
    const int blr  = tid >> 1;             // 0..127  (n within tile)
    const int bk4  = (tid & 1) * 4;        // k offset 0/4
    const int gnb  = bn0 + blr;
    const bool bvalid = (gnb < N);
    const float* Bbase = Bw + (size_t)gnb * K + bk4;

    float aR[AE];
    float4 bR;

    // ---- prologue: load k-tile 0 ----
#pragma unroll
    for (int u = 0; u < AE; u++) {
        int e = tid + u * 256;
        int r = e >> 3, k = e & 7;
        aR[u] = A[(size_t)(bm0 + r) * lda + k];
    }
    bR = bvalid ? *(const float4*)Bbase : make_float4(0.f, 0.f, 0.f, 0.f);
#pragma unroll
    for (int u = 0; u < AE; u++) {
        int e = tid + u * 256;
        As[0][e & 7][e >> 3] = aR[u];
    }
    Bs[0][bk4 + 0][blr] = bR.x;
    Bs[0][bk4 + 1][blr] = bR.y;
    Bs[0][bk4 + 2][blr] = bR.z;
    Bs[0][bk4 + 3][blr] = bR.w;
    __syncthreads();

    float acc[MR][8];
#pragma unroll
    for (int i = 0; i < MR; i++)
#pragma unroll
        for (int j = 0; j < 8; j++) acc[i][j] = 0.f;

    const int KT = K / BK;
    int buf = 0;
    for (int kt = 0; kt < KT; kt++) {
        if (kt + 1 < KT) {
            const int k0 = (kt + 1) * BK;
#pragma unroll
            for (int u = 0; u < AE; u++) {
                int e = tid + u * 256;
                int r = e >> 3, k = e & 7;
                aR[u] = A[(size_t)(bm0 + r) * lda + k0 + k];
            }
            bR = bvalid ? *(const float4*)(Bbase + k0) : make_float4(0.f, 0.f, 0.f, 0.f);
        }
#pragma unroll
        for (int k = 0; k < BK; k++) {
            float a[MR], b[8];
            {
                float4 a0 = *(const float4*)&As[buf][k][ty * 4];
                a[0] = a0.x; a[1] = a0.y; a[2] = a0.z; a[3] = a0.w;
                if (MR == 8) {
                    float4 a1 = *(const float4*)&As[buf][k][ty * 4 + 64];
                    a[4] = a1.x; a[5] = a1.y; a[6] = a1.z; a[7] = a1.w;
                }
                float4 b0 = *(const float4*)&Bs[buf][k][tx * 4];
                float4 b1 = *(const float4*)&Bs[buf][k][tx * 4 + 64];
                b[0] = b0.x; b[1] = b0.y; b[2] = b0.z; b[3] = b0.w;
                b[4] = b1.x; b[5] = b1.y; b[6] = b1.z; b[7] = b1.w;
            }
#pragma unroll
            for (int i = 0; i < MR; i++)
#pragma unroll
                for (int j = 0; j < 8; j++)
                    acc[i][j] = fmaf(a[i], b[j], acc[i][j]);
        }
        if (kt + 1 < KT) {
            int nb = buf ^ 1;
#pragma unroll
            for (int u = 0; u < AE; u++) {
                int e = tid + u * 256;
                As[nb][e & 7][e >> 3] = aR[u];
            }
            Bs[nb][bk4 + 0][blr] = bR.x;
            Bs[nb][bk4 + 1][blr] = bR.y;
            Bs[nb][bk4 + 2][blr] = bR.z;
            Bs[nb][bk4 + 3][blr] = bR.w;
            __syncthreads();
            buf = nb;
        }
    }

    // ---- epilogue ----
#pragma unroll
    for (int i = 0; i < MR; i++) {
        int gm = bm0 + ty * 4 + (i & 3) + (i >> 2) * 64;
#pragma unroll
        for (int jj = 0; jj < 2; jj++) {
            int gn = bn0 + tx * 4 + jj * 64;
            if (gn >= N) continue;
            float v0 = acc[i][jj * 4 + 0];
            float v1 = acc[i][jj * 4 + 1];
            float v2 = acc[i][jj * 4 + 2];
            float v3 = acc[i][jj * 4 + 3];
            float* cp = C + (size_t)gm * ldc + gn;
            if (EPI == 1) {
                float4 old = *(const float4*)cp;
                v0 += old.x; v1 += old.y; v2 += old.z; v3 += old.w;
            }
            if (EPI == 2) {
                float bb[4] = {bias[gn], bias[gn + 1], bias[gn + 2], bias[gn + 3]};
                v0 += bb[0]; v1 += bb[1]; v2 += bb[2]; v3 += bb[3];
                v0 = fmaxf(v0, 0.f) + log1pf(expf(-fabsf(v0)));
                v1 = fmaxf(v1, 0.f) + log1pf(expf(-fabsf(v1)));
                v2 = fmaxf(v2, 0.f) + log1pf(expf(-fabsf(v2)));
                v3 = fmaxf(v3, 0.f) + log1pf(expf(-fabsf(v3)));
            }
            *(float4*)cp = make_float4(v0, v1, v2, v3);
        }
    }
}

// =====================================================================
// x_proj split-K GEMM: part[z][M,80] = xc[:, z*KC:(z+1)*KC] @ W[:, zKC..]^T
// 64x64x16 tile, grid (2, M/64, 8)
// =====================================================================
__global__ void gemm_xproj_splitk(const float* __restrict__ A,   // [2048,1536]
                                  const float* __restrict__ Bw,  // [80,1536]
                                  float* __restrict__ part) {    // [8][2048][80]
    constexpr int BM = 64, BN = 64, BK = 16;
    __shared__ float As[BK][BM + 4];
    __shared__ float Bs[BK][BN + 4];
    const int tid = threadIdx.x;
    const int bm0 = blockIdx.y * BM;
    const int bn0 = blockIdx.x * BN;
    const int zoff = blockIdx.z * kXPKC;
    const int tx = tid & 15;
    const int ty = tid >> 4;
    float acc[4][4] = {};

    for (int k0 = 0; k0 < kXPKC; k0 += BK) {
#pragma unroll
        for (int t = tid; t < BM * BK; t += 256) {
            int m = t >> 4, k = t & 15;
            As[k][m] = A[(size_t)(bm0 + m) * kDI + zoff + k0 + k];
        }
#pragma unroll
        for (int t = tid; t < BN * BK; t += 256) {
            int n = t >> 4, k = t & 15;
            int gn = bn0 + n;
            Bs[k][n] = (gn < kDBC) ? Bw[(size_t)gn * kDI + zoff + k0 + k] : 0.f;
        }
        __syncthreads();
#pragma unroll
        for (int k = 0; k < BK; k++) {
            float a[4], b[4];
#pragma unroll
            for (int i = 0; i < 4; i++) a[i] = As[k][ty * 4 + i];
#pragma unroll
            for (int j = 0; j < 4; j++) b[j] = Bs[k][tx * 4 + j];
#pragma unroll
            for (int i = 0; i < 4; i++)
#pragma unroll
                for (int j = 0; j < 4; j++)
                    acc[i][j] = fmaf(a[i], b[j], acc[i][j]);
        }
        __syncthreads();
    }

    float* base = part + (size_t)blockIdx.z * kRows * kDBC;
#pragma unroll
    for (int i = 0; i < 4; i++) {
        int gm = bm0 + ty * 4 + i;
#pragma unroll
        for (int j = 0; j < 4; j++) {
            int gn = bn0 + tx * 4 + j;
            if (gn < kDBC) base[(size_t)gm * kDBC + gn] = acc[i][j];
        }
    }
}

__global__ void reduce_dbc_kernel(const float* __restrict__ part,
                                  float* __restrict__ dbc) {
    int idx = blockIdx.x * blockDim.x + threadIdx.x;
    if (idx >= kRows * kDBC) return;
    float s = 0.f;
#pragma unroll
    for (int z = 0; z < kXPChunks; z++)
        s += part[(size_t)z * kRows * kDBC + idx];
    dbc[idx] = s;
}

// ---------------- causal depthwise conv (DC=4) + SiLU ----------------
__global__ void conv_silu_kernel(const float* __restrict__ xz,
                                 const float* __restrict__ cw,
                                 const float* __restrict__ cb,
                                 float* __restrict__ xc) {
    int idx = blockIdx.x * blockDim.x + threadIdx.x;
    if (idx >= kRows * kDI) return;
    int i = idx % kDI;
    int r = idx / kDI;          // b*L + l
    int l = r % kL;
    int b = r / kL;
    float acc = cb[i];
#pragma unroll
    for (int k = 0; k < kDC; k++) {
        int ls = l + k - (kDC - 1);
        if (ls >= 0)
            acc = fmaf(xz[((size_t)(b * kL + ls)) * (2 * kDI) + i], cw[i * kDC + k], acc);
    }
    xc[idx] = acc / (1.f + __expf(-acc));
}

// ---------------- selective scan ----------------
__global__ void scan_kernel(const float* __restrict__ dt,
                            const float* __restrict__ xc,
                            const float* __restrict__ dbc,
                            const float* __restrict__ xz,
                            const float* __restrict__ A_log,
                            const float* __restrict__ D_skip,
                            float* __restrict__ y) {
    const int tid = threadIdx.x;
    const int s = tid & (kDS - 1);
    const int cglob = blockIdx.x * (blockDim.x / kDS) + (tid >> 4);
    const int b = cglob / kDI;
    const int i = cglob - b * kDI;

    const float a   = -__expf(A_log[i * kDS + s]);
    const float dsk = D_skip[i];

    constexpr int PF = 4;
    float fdt[PF], fx[PF], fB[PF], fC[PF];

    const size_t base_row = (size_t)b * kL;
#pragma unroll
    for (int j = 0; j < PF; j++) {
        size_t r = base_row + j;
        fdt[j] = dt [r * kDI + i];
        fx [j] = xc [r * kDI + i];
        fB [j] = dbc[r * kDBC + kDTR + s];
        fC [j] = dbc[r * kDBC + kDTR + kDS + s];
    }

    float h = 0.f;
#pragma unroll 4
    for (int l = 0; l < kL; l++) {
        const int slot = l & (PF - 1);
        float dt_t = fdt[slot];
        float x_t  = fx[slot];
        float Bt   = fB[slot];
        float Ct   = fC[slot];

        int ln = l + PF;
        if (ln < kL) {
            size_t r = base_row + ln;
            fdt[slot] = dt [r * kDI + i];
            fx [slot] = xc [r * kDI + i];
            fB [slot] = dbc[r * kDBC + kDTR + s];
            fC [slot] = dbc[r * kDBC + kDTR + kDS + s];
        }

        h = fmaf(h, __expf(dt_t * a), dt_t * x_t * Bt);
        float p = h * Ct;
        p += __shfl_xor_sync(0xffffffffu, p, 8);
        p += __shfl_xor_sync(0xffffffffu, p, 4);
        p += __shfl_xor_sync(0xffffffffu, p, 2);
        p += __shfl_xor_sync(0xffffffffu, p, 1);
        if (s == 0) {
            size_t r = base_row + l;
            float z = xz[r * (2 * kDI) + kDI + i];
            float yy = fmaf(x_t, dsk, p);
            yy *= z / (1.f + __expf(-z));
            y[r * kDI + i] = yy;
        }
    }
}

// ---------------- final head ----------------
__global__ void head_kernel(const float* __restrict__ xn,
                            const float* __restrict__ cls_w,
                            const float* __restrict__ cls_b,
                            float* __restrict__ out) {
    int b = blockIdx.x;
    __shared__ float mean[kD];
    for (int d = threadIdx.x; d < kD; d += blockDim.x) {
        float s = 0.f;
        const float* p = xn + ((size_t)b * kL) * kD + d;
        for (int l = 0; l < kL; l++) s += p[(size_t)l * kD];
        mean[d] = s / (float)kL;
    }
    __syncthreads();
    if (threadIdx.x < kNC) {
        int c = threadIdx.x;
        float s = cls_b[c];
        for (int d = 0; d < kD; d++) s = fmaf(mean[d], cls_w[c * kD + d], s);
        out[b * kNC + c] = s;
    }
}

// ---------------- launch ----------------
extern "C" void kernel_launch(void* const* d_in, const int* in_sizes, int n_in,
                              void* d_out, int out_size) {
    const int*   input_ids = (const int*)  d_in[0];
    const float* embed     = (const float*)d_in[1];
    const float* norm_w    = (const float*)d_in[2];
    const float* in_proj_w = (const float*)d_in[3];
    const float* conv_w    = (const float*)d_in[4];
    const float* conv_b    = (const float*)d_in[5];
    const float* x_proj_w  = (const float*)d_in[6];
    const float* dt_proj_w = (const float*)d_in[7];
    const float* dt_proj_b = (const float*)d_in[8];
    const float* A_log     = (const float*)d_in[9];
    const float* D_skip    = (const float*)d_in[10];
    const float* out_proj_w= (const float*)d_in[11];
    const float* norm_f_w  = (const float*)d_in[12];
    const float* cls_w     = (const float*)d_in[13];
    const float* cls_b     = (const float*)d_in[14];
    float* out = (float*)d_out;

    float *px, *pxn, *pxz, *pxc, *pdbc, *pdbp, *pdt, *py;
    cudaGetSymbolAddress((void**)&px,   g_x);
    cudaGetSymbolAddress((void**)&pxn,  g_xn);
    cudaGetSymbolAddress((void**)&pxz,  g_xz);
    cudaGetSymbolAddress((void**)&pxc,  g_xc);
    cudaGetSymbolAddress((void**)&pdbc, g_dbc);
    cudaGetSymbolAddress((void**)&pdbp, g_dbp);
    cudaGetSymbolAddress((void**)&pdt,  g_dt);
    cudaGetSymbolAddress((void**)&py,   g_y);

    // embedding
    {
        int total = kRows * kD / 4;
        embed_kernel<<<(total + 255) / 256, 256>>>(input_ids, embed, px);
    }

    for (int l = 0; l < kNL; l++) {
        const float* w_norm = norm_w    + (size_t)l * kD;
        const float* w_in   = in_proj_w + (size_t)l * 2 * kDI * kD;
        const float* w_cw   = conv_w    + (size_t)l * kDI * kDC;
        const float* w_cb   = conv_b    + (size_t)l * kDI;
        const float* w_xp   = x_proj_w  + (size_t)l * kDBC * kDI;
        const float* w_dtw  = dt_proj_w + (size_t)l * kDI * kDTR;
        const float* w_dtb  = dt_proj_b + (size_t)l * kDI;
        const float* w_Al   = A_log     + (size_t)l * kDI * kDS;
        const float* w_Dsk  = D_skip    + (size_t)l * kDI;
        const float* w_out  = out_proj_w+ (size_t)l * kD * kDI;

        // 1) rmsnorm
        rmsnorm_kernel<<<kRows, 256>>>(px, w_norm, pxn);

        // 2) in_proj: xz[2048,3072] = xn[2048,768] @ W^T   (BM=128)
        {
            dim3 grid(2 * kDI / 128, kRows / 128);
            sgemm_tn_kernel<0, 128><<<grid, 256>>>(pxn, kD, w_in, pxz, 2 * kDI,
                                                   nullptr, kRows, 2 * kDI, kD);
        }

        // 3) conv + silu
        {
            int total = kRows * kDI;
            conv_silu_kernel<<<(total + 255) / 256, 256>>>(pxz, w_cw, w_cb, pxc);
        }

        // 4) x_proj split-K: partials then reduce
        {
            dim3 grid(2, kRows / 64, kXPChunks);
            gemm_xproj_splitk<<<grid, 256>>>(pxc, w_xp, pdbp);
            int total = kRows * kDBC;
            reduce_dbc_kernel<<<(total + 255) / 256, 256>>>(pdbp, pdbc);
        }

        // 5) dt: dt[2048,1536] = softplus(dbc[:, :48] @ dtw^T + dtb)  (BM=128)
        {
            dim3 grid(kDI / 128, kRows / 128);
            sgemm_tn_kernel<2, 128><<<grid, 256>>>(pdbc, kDBC, w_dtw, pdt, kDI,
                                                   w_dtb, kRows, kDI, kDTR);
        }

        // 6) selective scan + D skip + SiLU gate
        {
            int blocks = (kB * kDI * kDS) / 256;   // 192
            scan_kernel<<<blocks, 256>>>(pdt, pxc, pdbc, pxz, w_Al, w_Dsk, py);
        }

        // 7) out_proj + residual: x[2048,768] += y @ W^T   (BM=64 -> 192 blocks)
        {
            dim3 grid(kD / 128, kRows / 64);
            sgemm_tn_kernel<1, 64><<<grid, 256>>>(py, kDI, w_out, px, kD,
                                                  nullptr, kRows, kD, kDI);
        }
    }

    // final norm + mean pool + classifier
    rmsnorm_kernel<<<kRows, 256>>>(px, norm_f_w, pxn);
    head_kernel<<<kB, 256>>>(pxn, cls_w, cls_b, out);
}

// round 3
// speedup vs baseline: 1.8990x; 1.4287x over previous
#include <cuda_runtime.h>
#include <cuda_bf16.h>
#include <math.h>
#include <stdint.h>

// ---------------- problem constants ----------------
constexpr int kV   = 50280;
constexpr int kD   = 768;
constexpr int kNL  = 8;
constexpr int kDI  = 1536;
constexpr int kDS  = 16;
constexpr int kDC  = 4;
constexpr int kDTR = 48;
constexpr int kNC  = 4;
constexpr int kB   = 2;
constexpr int kL   = 1024;
constexpr int kDBC = kDTR + 2 * kDS;  // 80
constexpr float kEPS = 1e-5f;

constexpr int kRows = kB * kL;        // 2048 token rows
constexpr int kXPChunks = 8;          // split-K chunks for x_proj
constexpr int kXPKC = kDI / kXPChunks; // 192

// ---------------- device scratch ----------------
__device__ float g_x  [kRows * kD];
__device__ float g_xn [kRows * kD];
__device__ float g_xz [kRows * 2 * kDI];
__device__ float g_xc [kRows * kDI];
__device__ float g_dbc[kRows * kDBC];
__device__ float g_dbp[kXPChunks * kRows * kDBC];
__device__ float g_dt [kRows * kDI];
__device__ float g_y  [kRows * kDI];

// ---------------- helpers ----------------
__device__ __forceinline__ float warp_sum(float v) {
#pragma unroll
    for (int o = 16; o > 0; o >>= 1) v += __shfl_xor_sync(0xffffffffu, v, o);
    return v;
}

__device__ __forceinline__ uint32_t smem_u32(const void* p) {
    return (uint32_t)__cvta_generic_to_shared(p);
}

__device__ __forceinline__ void ldmat_x4(uint32_t& r0, uint32_t& r1,
                                         uint32_t& r2, uint32_t& r3,
                                         uint32_t addr) {
    asm volatile("ldmatrix.sync.aligned.m8n8.x4.shared.b16 {%0,%1,%2,%3}, [%4];"
                 : "=r"(r0), "=r"(r1), "=r"(r2), "=r"(r3) : "r"(addr));
}

__device__ __forceinline__ void mma16816(float* c, const uint32_t* a,
                                         uint32_t b0, uint32_t b1) {
    asm volatile(
        "mma.sync.aligned.m16n8k16.row.col.f32.bf16.bf16.f32 "
        "{%0,%1,%2,%3}, {%4,%5,%6,%7}, {%8,%9}, {%0,%1,%2,%3};"
        : "+f"(c[0]), "+f"(c[1]), "+f"(c[2]), "+f"(c[3])
        : "r"(a[0]), "r"(a[1]), "r"(a[2]), "r"(a[3]), "r"(b0), "r"(b1));
}

__device__ __forceinline__ uint32_t pack_hi(float x, float y) {
    __nv_bfloat162 p = __floats2bfloat162_rn(x, y);
    return *(uint32_t*)&p;
}

// ---------------- embed gather ----------------
__global__ void embed_kernel(const int* __restrict__ ids,
                             const float* __restrict__ embed,
                             float* __restrict__ x) {
    int idx = blockIdx.x * blockDim.x + threadIdx.x;
    int total = kRows * kD / 4;
    if (idx >= total) return;
    int row = idx / (kD / 4);
    int d4 = idx - row * (kD / 4);
    const float4* src = (const float4*)(embed + (size_t)ids[row] * kD);
    ((float4*)x)[idx] = src[d4];
}

// ---------------- rmsnorm ----------------
__global__ void rmsnorm_kernel(const float* __restrict__ x,
                               const float* __restrict__ w,
                               float* __restrict__ out) {
    int row = blockIdx.x;
    const float* xr = x + (size_t)row * kD;
    float s = 0.f;
    for (int d = threadIdx.x; d < kD; d += blockDim.x) {
        float v = xr[d];
        s = fmaf(v, v, s);
    }
    s = warp_sum(s);
    __shared__ float sh[8];
    __shared__ float inv_s;
    int wid = threadIdx.x >> 5, lane = threadIdx.x & 31;
    if (lane == 0) sh[wid] = s;
    __syncthreads();
    if (wid == 0) {
        float t = (lane < (blockDim.x >> 5)) ? sh[lane] : 0.f;
        t = warp_sum(t);
        if (lane == 0) inv_s = rsqrtf(t / (float)kD + kEPS);
    }
    __syncthreads();
    float inv = inv_s;
    for (int d = threadIdx.x; d < kD; d += blockDim.x)
        out[(size_t)row * kD + d] = xr[d] * inv * w[d];
}

// =====================================================================
// Tensor-core GEMM with hi/lo bf16 split (fp32-grade precision).
//   C[M,N] = A[M,K(lda)] @ Bw[N,K]^T
//   BM in {64,128}, BN=128, BK=32, 256 threads (8 warps: 2 in M, 4 in N)
//   warp tile (BM/2)x32;  3 MMAs per position: hi*hi + hi*lo + lo*hi
// Requires: M%BM==0, N%BN==0, K%BK==0, A/Bw/C 16B-aligned rows.
// EPI 0: store    EPI 1: C += result
// =====================================================================
template <int EPI, int BM>
__global__ __launch_bounds__(256)
void hgemm_tn_kernel(const float* __restrict__ A, int lda,
                     const float* __restrict__ Bw,
                     float* __restrict__ C, int ldc,
                     int M, int N, int K) {
    constexpr int BN = 128, BK = 32;
    constexpr int STR = 40;                // bf16 stride (80B rows, swizzle-safe)
    constexpr int WM = BM / 2;             // 64 or 32
    constexpr int MF = WM / 16;            // 4 or 2 m-frags per warp
    constexpr int AF4 = BM * BK / 1024;    // float4 loads per thread for A (4 or 2)

    __shared__ __nv_bfloat16 Ah[BM][STR];
    __shared__ __nv_bfloat16 Al[BM][STR];
    __shared__ __nv_bfloat16 Bh[BN][STR];
    __shared__ __nv_bfloat16 Bl[BN][STR];

    const int tid = threadIdx.x;
    const int wid = tid >> 5, lane = tid & 31;
    const int bm0 = blockIdx.y * BM;
    const int bn0 = blockIdx.x * BN;
    const int wm = wid & 1;    // warp row (2)
    const int wn = wid >> 1;   // warp col (4)

    float acc[MF][4][4];
#pragma unroll
    for (int i = 0; i < MF; i++)
#pragma unroll
        for (int j = 0; j < 4; j++)
#pragma unroll
            for (int v = 0; v < 4; v++) acc[i][j][v] = 0.f;

    // ---- prefetch registers ----
    float4 aR[AF4], bR[4];

    auto load_tile = [&](int k0) {
#pragma unroll
        for (int u = 0; u < AF4; u++) {
            int e = tid + u * 256;
            int r = e >> 3, c4 = e & 7;
            aR[u] = *(const float4*)(A + (size_t)(bm0 + r) * lda + k0 + c4 * 4);
        }
#pragma unroll
        for (int u = 0; u < 4; u++) {
            int e = tid + u * 256;
            int r = e >> 3, c4 = e & 7;
            bR[u] = *(const float4*)(Bw + (size_t)(bn0 + r) * K + k0 + c4 * 4);
        }
    };
    auto store_tile = [&]() {
#pragma unroll
        for (int u = 0; u < AF4; u++) {
            int e = tid + u * 256;
            int r = e >> 3, c = (e & 7) * 4;
            float4 v = aR[u];
            __nv_bfloat162 h01 = __floats2bfloat162_rn(v.x, v.y);
            __nv_bfloat162 h23 = __floats2bfloat162_rn(v.z, v.w);
            __nv_bfloat162 l01 = __floats2bfloat162_rn(v.x - __bfloat162float(h01.x),
                                                       v.y - __bfloat162float(h01.y));
            __nv_bfloat162 l23 = __floats2bfloat162_rn(v.z - __bfloat162float(h23.x),
                                                       v.w - __bfloat162float(h23.y));
            *(__nv_bfloat162*)&Ah[r][c]     = h01;
            *(__nv_bfloat162*)&Ah[r][c + 2] = h23;
            *(__nv_bfloat162*)&Al[r][c]     = l01;
            *(__nv_bfloat162*)&Al[r][c + 2] = l23;
        }
#pragma unroll
        for (int u = 0; u < 4; u++) {
            int e = tid + u * 256;
            int r = e >> 3, c = (e & 7) * 4;
            float4 v = bR[u];
            __nv_bfloat162 h01 = __floats2bfloat162_rn(v.x, v.y);
            __nv_bfloat162 h23 = __floats2bfloat162_rn(v.z, v.w);
            __nv_bfloat162 l01 = __floats2bfloat162_rn(v.x - __bfloat162float(h01.x),
                                                       v.y - __bfloat162float(h01.y));
            __nv_bfloat162 l23 = __floats2bfloat162_rn(v.z - __bfloat162float(h23.x),
                                                       v.w - __bfloat162float(h23.y));
            *(__nv_bfloat162*)&Bh[r][c]     = h01;
            *(__nv_bfloat162*)&Bh[r][c + 2] = h23;
            *(__nv_bfloat162*)&Bl[r][c]     = l01;
            *(__nv_bfloat162*)&Bl[r][c + 2] = l23;
        }
    };

    // ldmatrix base addresses (per-thread, fixed across k-tiles)
    const int a_row = wm * WM + (lane & 15);
    const int a_col8 = (lane >> 4) << 3;
    const int b_grp = lane >> 3;
    const int b_row = wn * 32 + ((b_grp >> 1) << 3) + (lane & 7);
    const int b_col8 = (b_grp & 1) << 3;

    load_tile(0);
    const int KT = K / BK;
    for (int kt = 0; kt < KT; kt++) {
        if (kt > 0) __syncthreads();       // protect smem reads of prev tile
        store_tile();
        __syncthreads();
        if (kt + 1 < KT) load_tile((kt + 1) * BK);

#pragma unroll
        for (int kk = 0; kk < 2; kk++) {
            uint32_t ah[MF][4], al[MF][4];
            uint32_t bh[4][2], bl[4][2];
#pragma unroll
            for (int i = 0; i < MF; i++) {
                uint32_t adr = smem_u32(&Ah[a_row + i * 16][kk * 16 + a_col8]);
                ldmat_x4(ah[i][0], ah[i][1], ah[i][2], ah[i][3], adr);
                uint32_t adl = smem_u32(&Al[a_row + i * 16][kk * 16 + a_col8]);
                ldmat_x4(al[i][0], al[i][1], al[i][2], al[i][3], adl);
            }
#pragma unroll
            for (int jj = 0; jj < 2; jj++) {
                uint32_t bdr = smem_u32(&Bh[b_row + jj * 16][kk * 16 + b_col8]);
                ldmat_x4(bh[jj * 2][0], bh[jj * 2][1],
                         bh[jj * 2 + 1][0], bh[jj * 2 + 1][1], bdr);
                uint32_t bdl = smem_u32(&Bl[b_row + jj * 16][kk * 16 + b_col8]);
                ldmat_x4(bl[jj * 2][0], bl[jj * 2][1],
                         bl[jj * 2 + 1][0], bl[jj * 2 + 1][1], bdl);
            }
#pragma unroll
            for (int i = 0; i < MF; i++)
#pragma unroll
                for (int j = 0; j < 4; j++) {
                    mma16816(acc[i][j], ah[i], bh[j][0], bh[j][1]);
                    mma16816(acc[i][j], ah[i], bl[j][0], bl[j][1]);
                    mma16816(acc[i][j], al[i], bh[j][0], bh[j][1]);
                }
        }
    }

    // ---- epilogue ----
    const int c_row = bm0 + wm * WM + (lane >> 2);
    const int c_col = bn0 + wn * 32 + (lane & 3) * 2;
#pragma unroll
    for (int i = 0; i < MF; i++) {
#pragma unroll
        for (int j = 0; j < 4; j++) {
#pragma unroll
            for (int half = 0; half < 2; half++) {
                int gm = c_row + i * 16 + half * 8;
                int gn = c_col + j * 8;
                float* cp = C + (size_t)gm * ldc + gn;
                float v0 = acc[i][j][half * 2 + 0];
                float v1 = acc[i][j][half * 2 + 1];
                if (EPI == 1) {
                    float2 old = *(const float2*)cp;
                    v0 += old.x; v1 += old.y;
                }
                *(float2*)cp = make_float2(v0, v1);
            }
        }
    }
}

// =====================================================================
// fp32 fallback GEMM (used for dt_proj; K=48)
// =====================================================================
template <int EPI, int BMt>
__global__ __launch_bounds__(256)
void sgemm_tn_kernel(const float* __restrict__ A, int lda,
                     const float* __restrict__ Bw,
                     float* __restrict__ C, int ldc,
                     const float* __restrict__ bias,
                     int M, int N, int K) {
    constexpr int BN = 128, BK = 8;
    constexpr int MR = BMt / 16;
    constexpr int AE = BMt * BK / 256;
    __shared__ float As[2][BK][BMt + 4];
    __shared__ float Bs[2][BK][BN + 4];

    const int tid = threadIdx.x;
    const int bm0 = blockIdx.y * BMt;
    const int bn0 = blockIdx.x * BN;
    const int tx = tid & 15;
    const int ty = tid >> 4;

    const int blr = tid >> 1;
    const int bk4 = (tid & 1) * 4;
    const int gnb = bn0 + blr;
    const bool bvalid = (gnb < N);
    const float* Bbase = Bw + (size_t)gnb * K + bk4;

    float aR[AE];
    float4 bR;

#pragma unroll
    for (int u = 0; u < AE; u++) {
        int e = tid + u * 256;
        int r = e >> 3, k = e & 7;
        aR[u] = A[(size_t)(bm0 + r) * lda + k];
    }
    bR = bvalid ? *(const float4*)Bbase : make_float4(0.f, 0.f, 0.f, 0.f);
#pragma unroll
    for (int u = 0; u < AE; u++) {
        int e = tid + u * 256;
        As[0][e & 7][e >> 3] = aR[u];
    }
    Bs[0][bk4 + 0][blr] = bR.x;
    Bs[0][bk4 + 1][blr] = bR.y;
    Bs[0][bk4 + 2][blr] = bR.z;
    Bs[0][bk4 + 3][blr] = bR.w;
    __syncthreads();

    float acc[MR][8];
#pragma unroll
    for (int i = 0; i < MR; i++)
#pragma unroll
        for (int j = 0; j < 8; j++) acc[i][j] = 0.f;

    const int KT = K / BK;
    int buf = 0;
    for (int kt = 0; kt < KT; kt++) {
        if (kt + 1 < KT) {
            const int k0 = (kt + 1) * BK;
#pragma unroll
            for (int u = 0; u < AE; u++) {
                int e = tid + u * 256;
                int r = e >> 3, k = e & 7;
                aR[u] = A[(size_t)(bm0 + r) * lda + k0 + k];
            }
            bR = bvalid ? *(const float4*)(Bbase + k0) : make_float4(0.f, 0.f, 0.f, 0.f);
        }
#pragma unroll
        for (int k = 0; k < BK; k++) {
            float a[MR], b[8];
            {
                float4 a0 = *(const float4*)&As[buf][k][ty * 4];
                a[0] = a0.x; a[1] = a0.y; a[2] = a0.z; a[3] = a0.w;
                if (MR == 8) {
                    float4 a1 = *(const float4*)&As[buf][k][ty * 4 + 64];
                    a[4] = a1.x; a[5] = a1.y; a[6] = a1.z; a[7] = a1.w;
                }
                float4 b0 = *(const float4*)&Bs[buf][k][tx * 4];
                float4 b1 = *(const float4*)&Bs[buf][k][tx * 4 + 64];
                b[0] = b0.x; b[1] = b0.y; b[2] = b0.z; b[3] = b0.w;
                b[4] = b1.x; b[5] = b1.y; b[6] = b1.z; b[7] = b1.w;
            }
#pragma unroll
            for (int i = 0; i < MR; i++)
#pragma unroll
                for (int j = 0; j < 8; j++)
                    acc[i][j] = fmaf(a[i], b[j], acc[i][j]);
        }
        if (kt + 1 < KT) {
            int nb = buf ^ 1;
#pragma unroll
            for (int u = 0; u < AE; u++) {
                int e = tid + u * 256;
                As[nb][e & 7][e >> 3] = aR[u];
            }
            Bs[nb][bk4 + 0][blr] = bR.x;
            Bs[nb][bk4 + 1][blr] = bR.y;
            Bs[nb][bk4 + 2][blr] = bR.z;
            Bs[nb][bk4 + 3][blr] = bR.w;
            __syncthreads();
            buf = nb;
        }
    }

#pragma unroll
    for (int i = 0; i < MR; i++) {
        int gm = bm0 + ty * 4 + (i & 3) + (i >> 2) * 64;
#pragma unroll
        for (int jj = 0; jj < 2; jj++) {
            int gn = bn0 + tx * 4 + jj * 64;
            if (gn >= N) continue;
            float v0 = acc[i][jj * 4 + 0];
            float v1 = acc[i][jj * 4 + 1];
            float v2 = acc[i][jj * 4 + 2];
            float v3 = acc[i][jj * 4 + 3];
            float* cp = C + (size_t)gm * ldc + gn;
            if (EPI == 1) {
                float4 old = *(const float4*)cp;
                v0 += old.x; v1 += old.y; v2 += old.z; v3 += old.w;
            }
            if (EPI == 2) {
                float bb[4] = {bias[gn], bias[gn + 1], bias[gn + 2], bias[gn + 3]};
                v0 += bb[0]; v1 += bb[1]; v2 += bb[2]; v3 += bb[3];
                v0 = fmaxf(v0, 0.f) + log1pf(expf(-fabsf(v0)));
                v1 = fmaxf(v1, 0.f) + log1pf(expf(-fabsf(v1)));
                v2 = fmaxf(v2, 0.f) + log1pf(expf(-fabsf(v2)));
                v3 = fmaxf(v3, 0.f) + log1pf(expf(-fabsf(v3)));
            }
            *(float4*)cp = make_float4(v0, v1, v2, v3);
        }
    }
}

// =====================================================================
// x_proj split-K GEMM + reduce
// =====================================================================
__global__ void gemm_xproj_splitk(const float* __restrict__ A,
                                  const float* __restrict__ Bw,
                                  float* __restrict__ part) {
    constexpr int BM = 64, BN = 64, BK = 16;
    __shared__ float As[BK][BM + 4];
    __shared__ float Bs[BK][BN + 4];
    const int tid = threadIdx.x;
    const int bm0 = blockIdx.y * BM;
    const int bn0 = blockIdx.x * BN;
    const int zoff = blockIdx.z * kXPKC;
    const int tx = tid & 15;
    const int ty = tid >> 4;
    float acc[4][4] = {};

    for (int k0 = 0; k0 < kXPKC; k0 += BK) {
#pragma unroll
        for (int t = tid; t < BM * BK; t += 256) {
            int m = t >> 4, k = t & 15;
            As[k][m] = A[(size_t)(bm0 + m) * kDI + zoff + k0 + k];
        }
#pragma unroll
        for (int t = tid; t < BN * BK; t += 256) {
            int n = t >> 4, k = t & 15;
            int gn = bn0 + n;
            Bs[k][n] = (gn < kDBC) ? Bw[(size_t)gn * kDI + zoff + k0 + k] : 0.f;
        }
        __syncthreads();
#pragma unroll
        for (int k = 0; k < BK; k++) {
            float a[4], b[4];
#pragma unroll
            for (int i = 0; i < 4; i++) a[i] = As[k][ty * 4 + i];
#pragma unroll
            for (int j = 0; j < 4; j++) b[j] = Bs[k][tx * 4 + j];
#pragma unroll
            for (int i = 0; i < 4; i++)
#pragma unroll
                for (int j = 0; j < 4; j++)
                    acc[i][j] = fmaf(a[i], b[j], acc[i][j]);
        }
        __syncthreads();
    }

    float* base = part + (size_t)blockIdx.z * kRows * kDBC;
#pragma unroll
    for (int i = 0; i < 4; i++) {
        int gm = bm0 + ty * 4 + i;
#pragma unroll
        for (int j = 0; j < 4; j++) {
            int gn = bn0 + tx * 4 + j;
            if (gn < kDBC) base[(size_t)gm * kDBC + gn] = acc[i][j];
        }
    }
}

__global__ void reduce_dbc_kernel(const float* __restrict__ part,
                                  float* __restrict__ dbc) {
    int idx = blockIdx.x * blockDim.x + threadIdx.x;
    if (idx >= kRows * kDBC) return;
    float s = 0.f;
#pragma unroll
    for (int z = 0; z < kXPChunks; z++)
        s += part[(size_t)z * kRows * kDBC + idx];
    dbc[idx] = s;
}

// ---------------- causal depthwise conv (DC=4) + SiLU ----------------
__global__ void conv_silu_kernel(const float* __restrict__ xz,
                                 const float* __restrict__ cw,
                                 const float* __restrict__ cb,
                                 float* __restrict__ xc) {
    int idx = blockIdx.x * blockDim.x + threadIdx.x;
    if (idx >= kRows * kDI) return;
    int i = idx % kDI;
    int r = idx / kDI;
    int l = r % kL;
    int b = r / kL;
    float acc = cb[i];
#pragma unroll
    for (int k = 0; k < kDC; k++) {
        int ls = l + k - (kDC - 1);
        if (ls >= 0)
            acc = fmaf(xz[((size_t)(b * kL + ls)) * (2 * kDI) + i], cw[i * kDC + k], acc);
    }
    xc[idx] = acc / (1.f + __expf(-acc));
}

// ---------------- selective scan ----------------
__global__ void scan_kernel(const float* __restrict__ dt,
                            const float* __restrict__ xc,
                            const float* __restrict__ dbc,
                            const float* __restrict__ xz,
                            const float* __restrict__ A_log,
                            const float* __restrict__ D_skip,
                            float* __restrict__ y) {
    const int tid = threadIdx.x;
    const int s = tid & (kDS - 1);
    const int cglob = blockIdx.x * (blockDim.x / kDS) + (tid >> 4);
    const int b = cglob / kDI;
    const int i = cglob - b * kDI;

    const float a   = -__expf(A_log[i * kDS + s]);
    const float dsk = D_skip[i];

    constexpr int PF = 4;
    float fdt[PF], fx[PF], fB[PF], fC[PF];

    const size_t base_row = (size_t)b * kL;
#pragma unroll
    for (int j = 0; j < PF; j++) {
        size_t r = base_row + j;
        fdt[j] = dt [r * kDI + i];
        fx [j] = xc [r * kDI + i];
        fB [j] = dbc[r * kDBC + kDTR + s];
        fC [j] = dbc[r * kDBC + kDTR + kDS + s];
    }

    float h = 0.f;
#pragma unroll 4
    for (int l = 0; l < kL; l++) {
        const int slot = l & (PF - 1);
        float dt_t = fdt[slot];
        float x_t  = fx[slot];
        float Bt   = fB[slot];
        float Ct   = fC[slot];

        int ln = l + PF;
        if (ln < kL) {
            size_t r = base_row + ln;
            fdt[slot] = dt [r * kDI + i];
            fx [slot] = xc [r * kDI + i];
            fB [slot] = dbc[r * kDBC + kDTR + s];
            fC [slot] = dbc[r * kDBC + kDTR + kDS + s];
        }

        h = fmaf(h, __expf(dt_t * a), dt_t * x_t * Bt);
        float p = h * Ct;
        p += __shfl_xor_sync(0xffffffffu, p, 8);
        p += __shfl_xor_sync(0xffffffffu, p, 4);
        p += __shfl_xor_sync(0xffffffffu, p, 2);
        p += __shfl_xor_sync(0xffffffffu, p, 1);
        if (s == 0) {
            size_t r = base_row + l;
            float z = xz[r * (2 * kDI) + kDI + i];
            float yy = fmaf(x_t, dsk, p);
            yy *= z / (1.f + __expf(-z));
            y[r * kDI + i] = yy;
        }
    }
}

// ---------------- final head ----------------
__global__ void head_kernel(const float* __restrict__ xn,
                            const float* __restrict__ cls_w,
                            const float* __restrict__ cls_b,
                            float* __restrict__ out) {
    int b = blockIdx.x;
    __shared__ float mean[kD];
    for (int d = threadIdx.x; d < kD; d += blockDim.x) {
        float s = 0.f;
        const float* p = xn + ((size_t)b * kL) * kD + d;
        for (int l = 0; l < kL; l++) s += p[(size_t)l * kD];
        mean[d] = s / (float)kL;
    }
    __syncthreads();
    if (threadIdx.x < kNC) {
        int c = threadIdx.x;
        float s = cls_b[c];
        for (int d = 0; d < kD; d++) s = fmaf(mean[d], cls_w[c * kD + d], s);
        out[b * kNC + c] = s;
    }
}

// ---------------- launch ----------------
extern "C" void kernel_launch(void* const* d_in, const int* in_sizes, int n_in,
                              void* d_out, int out_size) {
    const int*   input_ids = (const int*)  d_in[0];
    const float* embed     = (const float*)d_in[1];
    const float* norm_w    = (const float*)d_in[2];
    const float* in_proj_w = (const float*)d_in[3];
    const float* conv_w    = (const float*)d_in[4];
    const float* conv_b    = (const float*)d_in[5];
    const float* x_proj_w  = (const float*)d_in[6];
    const float* dt_proj_w = (const float*)d_in[7];
    const float* dt_proj_b = (const float*)d_in[8];
    const float* A_log     = (const float*)d_in[9];
    const float* D_skip    = (const float*)d_in[10];
    const float* out_proj_w= (const float*)d_in[11];
    const float* norm_f_w  = (const float*)d_in[12];
    const float* cls_w     = (const float*)d_in[13];
    const float* cls_b     = (const float*)d_in[14];
    float* out = (float*)d_out;

    float *px, *pxn, *pxz, *pxc, *pdbc, *pdbp, *pdt, *py;
    cudaGetSymbolAddress((void**)&px,   g_x);
    cudaGetSymbolAddress((void**)&pxn,  g_xn);
    cudaGetSymbolAddress((void**)&pxz,  g_xz);
    cudaGetSymbolAddress((void**)&pxc,  g_xc);
    cudaGetSymbolAddress((void**)&pdbc, g_dbc);
    cudaGetSymbolAddress((void**)&pdbp, g_dbp);
    cudaGetSymbolAddress((void**)&pdt,  g_dt);
    cudaGetSymbolAddress((void**)&py,   g_y);

    {
        int total = kRows * kD / 4;
        embed_kernel<<<(total + 255) / 256, 256>>>(input_ids, embed, px);
    }

    for (int l = 0; l < kNL; l++) {
        const float* w_norm = norm_w    + (size_t)l * kD;
        const float* w_in   = in_proj_w + (size_t)l * 2 * kDI * kD;
        const float* w_cw   = conv_w    + (size_t)l * kDI * kDC;
        const float* w_cb   = conv_b    + (size_t)l * kDI;
        const float* w_xp   = x_proj_w  + (size_t)l * kDBC * kDI;
        const float* w_dtw  = dt_proj_w + (size_t)l * kDI * kDTR;
        const float* w_dtb  = dt_proj_b + (size_t)l * kDI;
        const float* w_Al   = A_log     + (size_t)l * kDI * kDS;
        const float* w_Dsk  = D_skip    + (size_t)l * kDI;
        const float* w_out  = out_proj_w+ (size_t)l * kD * kDI;

        // 1) rmsnorm
        rmsnorm_kernel<<<kRows, 256>>>(px, w_norm, pxn);

        // 2) in_proj (tensor cores): xz[2048,3072] = xn @ W^T
        {
            dim3 grid(2 * kDI / 128, kRows / 128);   // (24,16)
            hgemm_tn_kernel<0, 128><<<grid, 256>>>(pxn, kD, w_in, pxz, 2 * kDI,
                                                   kRows, 2 * kDI, kD);
        }

        // 3) conv + silu
        {
            int total = kRows * kDI;
            conv_silu_kernel<<<(total + 255) / 256, 256>>>(pxz, w_cw, w_cb, pxc);
        }

        // 4) x_proj split-K
        {
            dim3 grid(2, kRows / 64, kXPChunks);
            gemm_xproj_splitk<<<grid, 256>>>(pxc, w_xp, pdbp);
            int total = kRows * kDBC;
            reduce_dbc_kernel<<<(total + 255) / 256, 256>>>(pdbp, pdbc);
        }

        // 5) dt (fp32, K=48): softplus(dbc[:, :48] @ dtw^T + dtb)
        {
            dim3 grid(kDI / 128, kRows / 128);
            sgemm_tn_kernel<2, 128><<<grid, 256>>>(pdbc, kDBC, w_dtw, pdt, kDI,
                                                   w_dtb, kRows, kDI, kDTR);
        }

        // 6) selective scan
        {
            int blocks = (kB * kDI * kDS) / 256;
            scan_kernel<<<blocks, 256>>>(pdt, pxc, pdbc, pxz, w_Al, w_Dsk, py);
        }

        // 7) out_proj + residual (tensor cores, BM=64 -> 192 blocks)
        {
            dim3 grid(kD / 128, kRows / 64);
            hgemm_tn_kernel<1, 64><<<grid, 256>>>(py, kDI, w_out, px, kD,
                                                  kRows, kD, kDI);
        }
    }

    rmsnorm_kernel<<<kRows, 256>>>(px, norm_f_w, pxn);
    head_kernel<<<kB, 256>>>(pxn, cls_w, cls_b, out);
}

// round 4
// speedup vs baseline: 1.9101x; 1.0058x over previous
#include <cuda_runtime.h>
#include <cuda_bf16.h>
#include <math.h>
#include <stdint.h>

// ---------------- problem constants ----------------
constexpr int kV   = 50280;
constexpr int kD   = 768;
constexpr int kNL  = 8;
constexpr int kDI  = 1536;
constexpr int kDS  = 16;
constexpr int kDC  = 4;
constexpr int kDTR = 48;
constexpr int kNC  = 4;
constexpr int kB   = 2;
constexpr int kL   = 1024;
constexpr int kDBC = kDTR + 2 * kDS;  // 80
constexpr float kEPS = 1e-5f;

constexpr int kRows = kB * kL;        // 2048 token rows
constexpr int kXPChunks = 8;          // split-K chunks for x_proj
constexpr int kXPKC = kDI / kXPChunks; // 192

// ---------------- device scratch ----------------
__device__ float g_x  [kRows * kD];
__device__ float g_xn [kRows * kD];
__device__ float g_xz [kRows * 2 * kDI];
__device__ float g_xc [kRows * kDI];
__device__ float g_dbc[kRows * kDBC];
__device__ float g_dbp[kXPChunks * kRows * kDBC];
__device__ float g_dt [kRows * kDI];
__device__ float g_y  [kRows * kDI];

// ---------------- helpers ----------------
__device__ __forceinline__ float warp_sum(float v) {
#pragma unroll
    for (int o = 16; o > 0; o >>= 1) v += __shfl_xor_sync(0xffffffffu, v, o);
    return v;
}

__device__ __forceinline__ uint32_t smem_u32(const void* p) {
    return (uint32_t)__cvta_generic_to_shared(p);
}

__device__ __forceinline__ void ldmat_x4(uint32_t& r0, uint32_t& r1,
                                         uint32_t& r2, uint32_t& r3,
                                         uint32_t addr) {
    asm volatile("ldmatrix.sync.aligned.m8n8.x4.shared.b16 {%0,%1,%2,%3}, [%4];"
                 : "=r"(r0), "=r"(r1), "=r"(r2), "=r"(r3) : "r"(addr));
}

__device__ __forceinline__ void mma16816(float* c, const uint32_t* a,
                                         uint32_t b0, uint32_t b1) {
    asm volatile(
        "mma.sync.aligned.m16n8k16.row.col.f32.bf16.bf16.f32 "
        "{%0,%1,%2,%3}, {%4,%5,%6,%7}, {%8,%9}, {%0,%1,%2,%3};"
        : "+f"(c[0]), "+f"(c[1]), "+f"(c[2]), "+f"(c[3])
        : "r"(a[0]), "r"(a[1]), "r"(a[2]), "r"(a[3]), "r"(b0), "r"(b1));
}

__device__ __forceinline__ uint32_t pack_hi(float x, float y) {
    __nv_bfloat162 p = __floats2bfloat162_rn(x, y);
    return *(uint32_t*)&p;
}

// ---------------- embed gather ----------------
__global__ void embed_kernel(const int* __restrict__ ids,
                             const float* __restrict__ embed,
                             float* __restrict__ x) {
    int idx = blockIdx.x * blockDim.x + threadIdx.x;
    int total = kRows * kD / 4;
    if (idx >= total) return;
    int row = idx / (kD / 4);
    int d4 = idx - row * (kD / 4);
    const float4* src = (const float4*)(embed + (size_t)ids[row] * kD);
    ((float4*)x)[idx] = src[d4];
}

// ---------------- rmsnorm ----------------
__global__ void rmsnorm_kernel(const float* __restrict__ x,
                               const float* __restrict__ w,
                               float* __restrict__ out) {
    int row = blockIdx.x;
    const float* xr = x + (size_t)row * kD;
    float s = 0.f;
    for (int d = threadIdx.x; d < kD; d += blockDim.x) {
        float v = xr[d];
        s = fmaf(v, v, s);
    }
    s = warp_sum(s);
    __shared__ float sh[8];
    __shared__ float inv_s;
    int wid = threadIdx.x >> 5, lane = threadIdx.x & 31;
    if (lane == 0) sh[wid] = s;
    __syncthreads();
    if (wid == 0) {
        float t = (lane < (blockDim.x >> 5)) ? sh[lane] : 0.f;
        t = warp_sum(t);
        if (lane == 0) inv_s = rsqrtf(t / (float)kD + kEPS);
    }
    __syncthreads();
    float inv = inv_s;
    for (int d = threadIdx.x; d < kD; d += blockDim.x)
        out[(size_t)row * kD + d] = xr[d] * inv * w[d];
}

// =====================================================================
// Tensor-core GEMM with hi/lo bf16 split (fp32-grade precision).
//   C[M,N] = A[M,K(lda)] @ Bw[N,K]^T
//   BM in {64,128}, BN=128, BK=32, 256 threads (8 warps: 2 in M, 4 in N)
//   warp tile (BM/2)x32;  3 MMAs per position: hi*hi + hi*lo + lo*hi
// Requires: M%BM==0, N%BN==0, K%BK==0, A/Bw/C 16B-aligned rows.
// EPI 0: store    EPI 1: C += result
// =====================================================================
template <int EPI, int BM>
__global__ __launch_bounds__(256)
void hgemm_tn_kernel(const float* __restrict__ A, int lda,
                     const float* __restrict__ Bw,
                     float* __restrict__ C, int ldc,
                     int M, int N, int K) {
    constexpr int BN = 128, BK = 32;
    constexpr int STR = 40;                // bf16 stride (80B rows, swizzle-safe)
    constexpr int WM = BM / 2;             // 64 or 32
    constexpr int MF = WM / 16;            // 4 or 2 m-frags per warp
    constexpr int AF4 = BM * BK / 1024;    // float4 loads per thread for A (4 or 2)

    __shared__ __nv_bfloat16 Ah[BM][STR];
    __shared__ __nv_bfloat16 Al[BM][STR];
    __shared__ __nv_bfloat16 Bh[BN][STR];
    __shared__ __nv_bfloat16 Bl[BN][STR];

    const int tid = threadIdx.x;
    const int wid = tid >> 5, lane = tid & 31;
    const int bm0 = blockIdx.y * BM;
    const int bn0 = blockIdx.x * BN;
    const int wm = wid & 1;    // warp row (2)
    const int wn = wid >> 1;   // warp col (4)

    float acc[MF][4][4];
#pragma unroll
    for (int i = 0; i < MF; i++)
#pragma unroll
        for (int j = 0; j < 4; j++)
#pragma unroll
            for (int v = 0; v < 4; v++) acc[i][j][v] = 0.f;

    // ---- prefetch registers ----
    float4 aR[AF4], bR[4];

    auto load_tile = [&](int k0) {
#pragma unroll
        for (int u = 0; u < AF4; u++) {
            int e = tid + u * 256;
            int r = e >> 3, c4 = e & 7;
            aR[u] = *(const float4*)(A + (size_t)(bm0 + r) * lda + k0 + c4 * 4);
        }
#pragma unroll
        for (int u = 0; u < 4; u++) {
            int e = tid + u * 256;
            int r = e >> 3, c4 = e & 7;
            bR[u] = *(const float4*)(Bw + (size_t)(bn0 + r) * K + k0 + c4 * 4);
        }
    };
    auto store_tile = [&]() {
#pragma unroll
        for (int u = 0; u < AF4; u++) {
            int e = tid + u * 256;
            int r = e >> 3, c = (e & 7) * 4;
            float4 v = aR[u];
            __nv_bfloat162 h01 = __floats2bfloat162_rn(v.x, v.y);
            __nv_bfloat162 h23 = __floats2bfloat162_rn(v.z, v.w);
            __nv_bfloat162 l01 = __floats2bfloat162_rn(v.x - __bfloat162float(h01.x),
                                                       v.y - __bfloat162float(h01.y));
            __nv_bfloat162 l23 = __floats2bfloat162_rn(v.z - __bfloat162float(h23.x),
                                                       v.w - __bfloat162float(h23.y));
            *(__nv_bfloat162*)&Ah[r][c]     = h01;
            *(__nv_bfloat162*)&Ah[r][c + 2] = h23;
            *(__nv_bfloat162*)&Al[r][c]     = l01;
            *(__nv_bfloat162*)&Al[r][c + 2] = l23;
        }
#pragma unroll
        for (int u = 0; u < 4; u++) {
            int e = tid + u * 256;
            int r = e >> 3, c = (e & 7) * 4;
            float4 v = bR[u];
            __nv_bfloat162 h01 = __floats2bfloat162_rn(v.x, v.y);
            __nv_bfloat162 h23 = __floats2bfloat162_rn(v.z, v.w);
            __nv_bfloat162 l01 = __floats2bfloat162_rn(v.x - __bfloat162float(h01.x),
                                                       v.y - __bfloat162float(h01.y));
            __nv_bfloat162 l23 = __floats2bfloat162_rn(v.z - __bfloat162float(h23.x),
                                                       v.w - __bfloat162float(h23.y));
            *(__nv_bfloat162*)&Bh[r][c]     = h01;
            *(__nv_bfloat162*)&Bh[r][c + 2] = h23;
            *(__nv_bfloat162*)&Bl[r][c]     = l01;
            *(__nv_bfloat162*)&Bl[r][c + 2] = l23;
        }
    };

    // ldmatrix base addresses (per-thread, fixed across k-tiles)
    const int a_row = wm * WM + (lane & 15);
    const int a_col8 = (lane >> 4) << 3;
    const int b_grp = lane >> 3;
    const int b_row = wn * 32 + ((b_grp >> 1) << 3) + (lane & 7);
    const int b_col8 = (b_grp & 1) << 3;

    load_tile(0);
    const int KT = K / BK;
    for (int kt = 0; kt < KT; kt++) {
        if (kt > 0) __syncthreads();       // protect smem reads of prev tile
        store_tile();
        __syncthreads();
        if (kt + 1 < KT) load_tile((kt + 1) * BK);

#pragma unroll
        for (int kk = 0; kk < 2; kk++) {
            uint32_t ah[MF][4], al[MF][4];
            uint32_t bh[4][2], bl[4][2];
#pragma unroll
            for (int i = 0; i < MF; i++) {
                uint32_t adr = smem_u32(&Ah[a_row + i * 16][kk * 16 + a_col8]);
                ldmat_x4(ah[i][0], ah[i][1], ah[i][2], ah[i][3], adr);
                uint32_t adl = smem_u32(&Al[a_row + i * 16][kk * 16 + a_col8]);
                ldmat_x4(al[i][0], al[i][1], al[i][2], al[i][3], adl);
            }
#pragma unroll
            for (int jj = 0; jj < 2; jj++) {
                uint32_t bdr = smem_u32(&Bh[b_row + jj * 16][kk * 16 + b_col8]);
                ldmat_x4(bh[jj * 2][0], bh[jj * 2][1],
                         bh[jj * 2 + 1][0], bh[jj * 2 + 1][1], bdr);
                uint32_t bdl = smem_u32(&Bl[b_row + jj * 16][kk * 16 + b_col8]);
                ldmat_x4(bl[jj * 2][0], bl[jj * 2][1],
                         bl[jj * 2 + 1][0], bl[jj * 2 + 1][1], bdl);
            }
#pragma unroll
            for (int i = 0; i < MF; i++)
#pragma unroll
                for (int j = 0; j < 4; j++) {
                    mma16816(acc[i][j], ah[i], bh[j][0], bh[j][1]);
                    mma16816(acc[i][j], ah[i], bl[j][0], bl[j][1]);
                    mma16816(acc[i][j], al[i], bh[j][0], bh[j][1]);
                }
        }
    }

    // ---- epilogue ----
    const int c_row = bm0 + wm * WM + (lane >> 2);
    const int c_col = bn0 + wn * 32 + (lane & 3) * 2;
#pragma unroll
    for (int i = 0; i < MF; i++) {
#pragma unroll
        for (int j = 0; j < 4; j++) {
#pragma unroll
            for (int half = 0; half < 2; half++) {
                int gm = c_row + i * 16 + half * 8;
                int gn = c_col + j * 8;
                float* cp = C + (size_t)gm * ldc + gn;
                float v0 = acc[i][j][half * 2 + 0];
                float v1 = acc[i][j][half * 2 + 1];
                if (EPI == 1) {
                    float2 old = *(const float2*)cp;
                    v0 += old.x; v1 += old.y;
                }
                *(float2*)cp = make_float2(v0, v1);
            }
        }
    }
}

// =====================================================================
// fp32 fallback GEMM (used for dt_proj; K=48)
// =====================================================================
template <int EPI, int BMt>
__global__ __launch_bounds__(256)
void sgemm_tn_kernel(const float* __restrict__ A, int lda,
                     const float* __restrict__ Bw,
                     float* __restrict__ C, int ldc,
                     const float* __restrict__ bias,
                     int M, int N, int K) {
    constexpr int BN = 128, BK = 8;
    constexpr int MR = BMt / 16;
    constexpr int AE = BMt * BK / 256;
    __shared__ float As[2][BK][BMt + 4];
    __shared__ float Bs[2][BK][BN + 4];

    const int tid = threadIdx.x;
    const int bm0 = blockIdx.y * BMt;
    const int bn0 = blockIdx.x * BN;
    const int tx = tid & 15;
    const int ty = tid >> 4;

    const int blr = tid >> 1;
    const int bk4 = (tid & 1) * 4;
    const int gnb = bn0 + blr;
    const bool bvalid = (gnb < N);
    const float* Bbase = Bw + (size_t)gnb * K + bk4;

    float aR[AE];
    float4 bR;

#pragma unroll
    for (int u = 0; u < AE; u++) {
        int e = tid + u * 256;
        int r = e >> 3, k = e & 7;
        aR[u] = A[(size_t)(bm0 + r) * lda + k];
    }
    bR = bvalid ? *(const float4*)Bbase : make_float4(0.f, 0.f, 0.f, 0.f);
#pragma unroll
    for (int u = 0; u < AE; u++) {
        int e = tid + u * 256;
        As[0][e & 7][e >> 3] = aR[u];
    }
    Bs[0][bk4 + 0][blr] = bR.x;
    Bs[0][bk4 + 1][blr] = bR.y;
    Bs[0][bk4 + 2][blr] = bR.z;
    Bs[0][bk4 + 3][blr] = bR.w;
    __syncthreads();

    float acc[MR][8];
#pragma unroll
    for (int i = 0; i < MR; i++)
#pragma unroll
        for (int j = 0; j < 8; j++) acc[i][j] = 0.f;

    const int KT = K / BK;
    int buf = 0;
    for (int kt = 0; kt < KT; kt++) {
        if (kt + 1 < KT) {
            const int k0 = (kt + 1) * BK;
#pragma unroll
            for (int u = 0; u < AE; u++) {
                int e = tid + u * 256;
                int r = e >> 3, k = e & 7;
                aR[u] = A[(size_t)(bm0 + r) * lda + k0 + k];
            }
            bR = bvalid ? *(const float4*)(Bbase + k0) : make_float4(0.f, 0.f, 0.f, 0.f);
        }
#pragma unroll
        for (int k = 0; k < BK; k++) {
            float a[MR], b[8];
            {
                float4 a0 = *(const float4*)&As[buf][k][ty * 4];
                a[0] = a0.x; a[1] = a0.y; a[2] = a0.z; a[3] = a0.w;
                if (MR == 8) {
                    float4 a1 = *(const float4*)&As[buf][k][ty * 4 + 64];
                    a[4] = a1.x; a[5] = a1.y; a[6] = a1.z; a[7] = a1.w;
                }
                float4 b0 = *(const float4*)&Bs[buf][k][tx * 4];
                float4 b1 = *(const float4*)&Bs[buf][k][tx * 4 + 64];
                b[0] = b0.x; b[1] = b0.y; b[2] = b0.z; b[3] = b0.w;
                b[4] = b1.x; b[5] = b1.y; b[6] = b1.z; b[7] = b1.w;
            }
#pragma unroll
            for (int i = 0; i < MR; i++)
#pragma unroll
                for (int j = 0; j < 8; j++)
                    acc[i][j] = fmaf(a[i], b[j], acc[i][j]);
        }
        if (kt + 1 < KT) {
            int nb = buf ^ 1;
#pragma unroll
            for (int u = 0; u < AE; u++) {
                int e = tid + u * 256;
                As[nb][e & 7][e >> 3] = aR[u];
            }
            Bs[nb][bk4 + 0][blr] = bR.x;
            Bs[nb][bk4 + 1][blr] = bR.y;
            Bs[nb][bk4 + 2][blr] = bR.z;
            Bs[nb][bk4 + 3][blr] = bR.w;
            __syncthreads();
            buf = nb;
        }
    }

#pragma unroll
    for (int i = 0; i < MR; i++) {
        int gm = bm0 + ty * 4 + (i & 3) + (i >> 2) * 64;
#pragma unroll
        for (int jj = 0; jj < 2; jj++) {
            int gn = bn0 + tx * 4 + jj * 64;
            if (gn >= N) continue;
            float v0 = acc[i][jj * 4 + 0];
            float v1 = acc[i][jj * 4 + 1];
            float v2 = acc[i][jj * 4 + 2];
            float v3 = acc[i][jj * 4 + 3];
            float* cp = C + (size_t)gm * ldc + gn;
            if (EPI == 1) {
                float4 old = *(const float4*)cp;
                v0 += old.x; v1 += old.y; v2 += old.z; v3 += old.w;
            }
            if (EPI == 2) {
                float bb[4] = {bias[gn], bias[gn + 1], bias[gn + 2], bias[gn + 3]};
                v0 += bb[0]; v1 += bb[1]; v2 += bb[2]; v3 += bb[3];
                v0 = fmaxf(v0, 0.f) + log1pf(expf(-fabsf(v0)));
                v1 = fmaxf(v1, 0.f) + log1pf(expf(-fabsf(v1)));
                v2 = fmaxf(v2, 0.f) + log1pf(expf(-fabsf(v2)));
                v3 = fmaxf(v3, 0.f) + log1pf(expf(-fabsf(v3)));
            }
            *(float4*)cp = make_float4(v0, v1, v2, v3);
        }
    }
}

// =====================================================================
// x_proj split-K GEMM + reduce
// =====================================================================
__global__ void gemm_xproj_splitk(const float* __restrict__ A,
                                  const float* __restrict__ Bw,
                                  float* __restrict__ part) {
    constexpr int BM = 64, BN = 64, BK = 16;
    __shared__ float As[BK][BM + 4];
    __shared__ float Bs[BK][BN + 4];
    const int tid = threadIdx.x;
    const int bm0 = blockIdx.y * BM;
    const int bn0 = blockIdx.x * BN;
    const int zoff = blockIdx.z * kXPKC;
    const int tx = tid & 15;
    const int ty = tid >> 4;
    float acc[4][4] = {};

    for (int k0 = 0; k0 < kXPKC; k0 += BK) {
#pragma unroll
        for (int t = tid; t < BM * BK; t += 256) {
            int m = t >> 4, k = t & 15;
            As[k][m] = A[(size_t)(bm0 + m) * kDI + zoff + k0 + k];
        }
#pragma unroll
        for (int t = tid; t < BN * BK; t += 256) {
            int n = t >> 4, k = t & 15;
            int gn = bn0 + n;
            Bs[k][n] = (gn < kDBC) ? Bw[(size_t)gn * kDI + zoff + k0 + k] : 0.f;
        }
        __syncthreads();
#pragma unroll
        for (int k = 0; k < BK; k++) {
            float a[4], b[4];
#pragma unroll
            for (int i = 0; i < 4; i++) a[i] = As[k][ty * 4 + i];
#pragma unroll
            for (int j = 0; j < 4; j++) b[j] = Bs[k][tx * 4 + j];
#pragma unroll
            for (int i = 0; i < 4; i++)
#pragma unroll
                for (int j = 0; j < 4; j++)
                    acc[i][j] = fmaf(a[i], b[j], acc[i][j]);
        }
        __syncthreads();
    }

    float* base = part + (size_t)blockIdx.z * kRows * kDBC;
#pragma unroll
    for (int i = 0; i < 4; i++) {
        int gm = bm0 + ty * 4 + i;
#pragma unroll
        for (int j = 0; j < 4; j++) {
            int gn = bn0 + tx * 4 + j;
            if (gn < kDBC) base[(size_t)gm * kDBC + gn] = acc[i][j];
        }
    }
}

__global__ void reduce_dbc_kernel(const float* __restrict__ part,
                                  float* __restrict__ dbc) {
    int idx = blockIdx.x * blockDim.x + threadIdx.x;
    if (idx >= kRows * kDBC) return;
    float s = 0.f;
#pragma unroll
    for (int z = 0; z < kXPChunks; z++)
        s += part[(size_t)z * kRows * kDBC + idx];
    dbc[idx] = s;
}

// ---------------- causal depthwise conv (DC=4) + SiLU ----------------
__global__ void conv_silu_kernel(const float* __restrict__ xz,
                                 const float* __restrict__ cw,
                                 const float* __restrict__ cb,
                                 float* __restrict__ xc) {
    int idx = blockIdx.x * blockDim.x + threadIdx.x;
    if (idx >= kRows * kDI) return;
    int i = idx % kDI;
    int r = idx / kDI;
    int l = r % kL;
    int b = r / kL;
    float acc = cb[i];
#pragma unroll
    for (int k = 0; k < kDC; k++) {
        int ls = l + k - (kDC - 1);
        if (ls >= 0)
            acc = fmaf(xz[((size_t)(b * kL + ls)) * (2 * kDI) + i], cw[i * kDC + k], acc);
    }
    xc[idx] = acc / (1.f + __expf(-acc));
}

// ---------------- selective scan ----------------
__global__ void scan_kernel(const float* __restrict__ dt,
                            const float* __restrict__ xc,
                            const float* __restrict__ dbc,
                            const float* __restrict__ xz,
                            const float* __restrict__ A_log,
                            const float* __restrict__ D_skip,
                            float* __restrict__ y) {
    const int tid = threadIdx.x;
    const int s = tid & (kDS - 1);
    const int cglob = blockIdx.x * (blockDim.x / kDS) + (tid >> 4);
    const int b = cglob / kDI;
    const int i = cglob - b * kDI;

    const float a   = -__expf(A_log[i * kDS + s]);
    const float dsk = D_skip[i];

    constexpr int PF = 4;
    float fdt[PF], fx[PF], fB[PF], fC[PF];

    const size_t base_row = (size_t)b * kL;
#pragma unroll
    for (int j = 0; j < PF; j++) {
        size_t r = base_row + j;
        fdt[j] = dt [r * kDI + i];
        fx [j] = xc [r * kDI + i];
        fB [j] = dbc[r * kDBC + kDTR + s];
        fC [j] = dbc[r * kDBC + kDTR + kDS + s];
    }

    float h = 0.f;
#pragma unroll 4
    for (int l = 0; l < kL; l++) {
        const int slot = l & (PF - 1);
        float dt_t = fdt[slot];
        float x_t  = fx[slot];
        float Bt   = fB[slot];
        float Ct   = fC[slot];

        int ln = l + PF;
        if (ln < kL) {
            size_t r = base_row + ln;
            fdt[slot] = dt [r * kDI + i];
            fx [slot] = xc [r * kDI + i];
            fB [slot] = dbc[r * kDBC + kDTR + s];
            fC [slot] = dbc[r * kDBC + kDTR + kDS + s];
        }

        h = fmaf(h, __expf(dt_t * a), dt_t * x_t * Bt);
        float p = h * Ct;
        p += __shfl_xor_sync(0xffffffffu, p, 8);
        p += __shfl_xor_sync(0xffffffffu, p, 4);
        p += __shfl_xor_sync(0xffffffffu, p, 2);
        p += __shfl_xor_sync(0xffffffffu, p, 1);
        if (s == 0) {
            size_t r = base_row + l;
            float z = xz[r * (2 * kDI) + kDI + i];
            float yy = fmaf(x_t, dsk, p);
            yy *= z / (1.f + __expf(-z));
            y[r * kDI + i] = yy;
        }
    }
}

// ---------------- final head ----------------
__global__ void head_kernel(const float* __restrict__ xn,
                            const float* __restrict__ cls_w,
                            const float* __restrict__ cls_b,
                            float* __restrict__ out) {
    int b = blockIdx.x;
    __shared__ float mean[kD];
    for (int d = threadIdx.x; d < kD; d += blockDim.x) {
        float s = 0.f;
        const float* p = xn + ((size_t)b * kL) * kD + d;
        for (int l = 0; l < kL; l++) s += p[(size_t)l * kD];
        mean[d] = s / (float)kL;
    }
    __syncthreads();
    if (threadIdx.x < kNC) {
        int c = threadIdx.x;
        float s = cls_b[c];
        for (int d = 0; d < kD; d++) s = fmaf(mean[d], cls_w[c * kD + d], s);
        out[b * kNC + c] = s;
    }
}

// ---------------- launch ----------------
extern "C" void kernel_launch(void* const* d_in, const int* in_sizes, int n_in,
                              void* d_out, int out_size) {
    const int*   input_ids = (const int*)  d_in[0];
    const float* embed     = (const float*)d_in[1];
    const float* norm_w    = (const float*)d_in[2];
    const float* in_proj_w = (const float*)d_in[3];
    const float* conv_w    = (const float*)d_in[4];
    const float* conv_b    = (const float*)d_in[5];
    const float* x_proj_w  = (const float*)d_in[6];
    const float* dt_proj_w = (const float*)d_in[7];
    const float* dt_proj_b = (const float*)d_in[8];
    const float* A_log     = (const float*)d_in[9];
    const float* D_skip    = (const float*)d_in[10];
    const float* out_proj_w= (const float*)d_in[11];
    const float* norm_f_w  = (const float*)d_in[12];
    const float* cls_w     = (const float*)d_in[13];
    const float* cls_b     = (const float*)d_in[14];
    float* out = (float*)d_out;

    float *px, *pxn, *pxz, *pxc, *pdbc, *pdbp, *pdt, *py;
    cudaGetSymbolAddress((void**)&px,   g_x);
    cudaGetSymbolAddress((void**)&pxn,  g_xn);
    cudaGetSymbolAddress((void**)&pxz,  g_xz);
    cudaGetSymbolAddress((void**)&pxc,  g_xc);
    cudaGetSymbolAddress((void**)&pdbc, g_dbc);
    cudaGetSymbolAddress((void**)&pdbp, g_dbp);
    cudaGetSymbolAddress((void**)&pdt,  g_dt);
    cudaGetSymbolAddress((void**)&py,   g_y);

    {
        int total = kRows * kD / 4;
        embed_kernel<<<(total + 255) / 256, 256>>>(input_ids, embed, px);
    }

    for (int l = 0; l < kNL; l++) {
        const float* w_norm = norm_w    + (size_t)l * kD;
        const float* w_in   = in_proj_w + (size_t)l * 2 * kDI * kD;
        const float* w_cw   = conv_w    + (size_t)l * kDI * kDC;
        const float* w_cb   = conv_b    + (size_t)l * kDI;
        const float* w_xp   = x_proj_w  + (size_t)l * kDBC * kDI;
        const float* w_dtw  = dt_proj_w + (size_t)l * kDI * kDTR;
        const float* w_dtb  = dt_proj_b + (size_t)l * kDI;
        const float* w_Al   = A_log     + (size_t)l * kDI * kDS;
        const float* w_Dsk  = D_skip    + (size_t)l * kDI;
        const float* w_out  = out_proj_w+ (size_t)l * kD * kDI;

        // 1) rmsnorm
        rmsnorm_kernel<<<kRows, 256>>>(px, w_norm, pxn);

        // 2) in_proj (tensor cores): xz[2048,3072] = xn @ W^T
        {
            dim3 grid(2 * kDI / 128, kRows / 128);   // (24,16)
            hgemm_tn_kernel<0, 128><<<grid, 256>>>(pxn, kD, w_in, pxz, 2 * kDI,
                                                   kRows, 2 * kDI, kD);
        }

        // 3) conv + silu
        {
            int total = kRows * kDI;
            conv_silu_kernel<<<(total + 255) / 256, 256>>>(pxz, w_cw, w_cb, pxc);
        }

        // 4) x_proj split-K
        {
            dim3 grid(2, kRows / 64, kXPChunks);
            gemm_xproj_splitk<<<grid, 256>>>(pxc, w_xp, pdbp);
            int total = kRows * kDBC;
            reduce_dbc_kernel<<<(total + 255) / 256, 256>>>(pdbp, pdbc);
        }

        // 5) dt (fp32, K=48): softplus(dbc[:, :48] @ dtw^T + dtb)
        {
            dim3 grid(kDI / 128, kRows / 128);
            sgemm_tn_kernel<2, 128><<<grid, 256>>>(pdbc, kDBC, w_dtw, pdt, kDI,
                                                   w_dtb, kRows, kDI, kDTR);
        }

        // 6) selective scan
        {
            int blocks = (kB * kDI * kDS) / 256;
            scan_kernel<<<blocks, 256>>>(pdt, pxc, pdbc, pxz, w_Al, w_Dsk, py);
        }

        // 7) out_proj + residual (tensor cores, BM=64 -> 192 blocks)
        {
            dim3 grid(kD / 128, kRows / 64);
            hgemm_tn_kernel<1, 64><<<grid, 256>>>(py, kDI, w_out, px, kD,
                                                  kRows, kD, kDI);
        }
    }

    rmsnorm_kernel<<<kRows, 256>>>(px, norm_f_w, pxn);
    head_kernel<<<kB, 256>>>(pxn, cls_w, cls_b, out);
}